// round 11
// baseline (speedup 1.0000x reference)
#include <cuda_runtime.h>
#include <cuda_bf16.h>
#include <cstdint>
#include <math.h>

#define NROWS 102400      // BS * N_AGENTS
#define NBATCH 2048
#define QSIZE (NROWS * 8)

// ---------------- static scratch ----------------
// Split layout: row-major [rows][256] bf16, cols 0..127 = hi, 128..255 = lo.
__device__ __nv_bfloat16  g_xs[NROWS * 256];     // GCN output activations, split
__device__ float          g_gi[NROWS * 384];
__device__ __nv_bfloat16  g_wgs[128 * 256];      // w_gcn split
__device__ __nv_bfloat16  g_wihs[384 * 256];     // w_ih split
__device__ __nv_bfloat16  g_whhs[384 * 256];     // w_hh split

// ---------------- tile geometry ----------------
#define LDS_K 264     // K=256 hi|lo + 8 pad
#define BM 64
#define A_TILE (BM * LDS_K)
#define B_TILE (128 * LDS_K)
#define GEMM_SMEM ((A_TILE + B_TILE) * 2)  // 101376 B

// fused GCN smem layout:
//   bf16 Xs [128][264]   @ elem 0
//   bf16 Ws [128][264]   @ elem 33792
//   f32  Yf [2][52][132] @ byte 135168  (rows 50,51 zeroed guards)
//   f32  Af [52][52]
#define FX_OFF 0
#define FW_OFF (128 * LDS_K)
#define FYF_BYTE (2 * 128 * LDS_K * 2)           // 135168
#define FAF_FLT  (2 * 52 * 132)
#define FUSED_SMEM (FYF_BYTE + (FAF_FLT + 52 * 52) * 4)   // 200896 B

// ---------------- cp.async helpers ----------------
__device__ __forceinline__ uint32_t smem_u32(const void* p) {
    uint32_t a;
    asm("{ .reg .u64 t; cvta.to.shared.u64 t, %1; cvt.u32.u64 %0, t; }" : "=r"(a) : "l"(p));
    return a;
}
#define CP16(dst_u32, src_ptr) \
    asm volatile("cp.async.cg.shared.global [%0], [%1], 16;" :: "r"(dst_u32), "l"(src_ptr))
#define CP_COMMIT()  asm volatile("cp.async.commit_group;" ::: "memory")
#define CP_WAIT0()   asm volatile("cp.async.wait_group 0;" ::: "memory")

template <int ROWS, int NTHR>
__device__ __forceinline__ void fill_bf16_ca(__nv_bfloat16* S, const __nv_bfloat16* G,
                                             int tid) {
    uint32_t sb = smem_u32(S);
    const uint4* g = reinterpret_cast<const uint4*>(G);
    for (int i = tid; i < ROWS * 32; i += NTHR) {
        int r = i >> 5, c = i & 31;
        CP16(sb + (r * LDS_K + c * 8) * 2, g + r * 32 + c);
    }
}
__device__ __forceinline__ void split_store(__nv_bfloat16* S, int r, int c, float4 v) {
    __nv_bfloat16 h0 = __float2bfloat16(v.x), h1 = __float2bfloat16(v.y);
    __nv_bfloat16 h2 = __float2bfloat16(v.z), h3 = __float2bfloat16(v.w);
    __nv_bfloat162 H0{h0, h1}, H1{h2, h3};
    __nv_bfloat162 L0{__float2bfloat16(v.x - __bfloat162float(h0)),
                      __float2bfloat16(v.y - __bfloat162float(h1))};
    __nv_bfloat162 L1{__float2bfloat16(v.z - __bfloat162float(h2)),
                      __float2bfloat16(v.w - __bfloat162float(h3))};
    __nv_bfloat16* hp = &S[r * LDS_K + c * 4];
    __nv_bfloat16* lp = &S[r * LDS_K + 128 + c * 4];
    *reinterpret_cast<__nv_bfloat162*>(hp)     = H0;
    *reinterpret_cast<__nv_bfloat162*>(hp + 2) = H1;
    *reinterpret_cast<__nv_bfloat162*>(lp)     = L0;
    *reinterpret_cast<__nv_bfloat162*>(lp + 2) = L1;
}
__device__ __forceinline__ void fill_f32split(__nv_bfloat16* S, const float* G, int tid) {
    const float4* g = reinterpret_cast<const float4*>(G);
    for (int i = tid; i < BM * 32; i += 256) {
        int r = i >> 5, c = i & 31;
        split_store(S, r, c, g[r * 32 + c]);
    }
}

// ---------------------------------------------------------------------------
// Compensated MMA over [hi|lo] K=256 tiles (emulates fp32 via 3 bf16 passes).
// Warp tile 32 x (NT*8); MT=2.
// ---------------------------------------------------------------------------
template <int NT>
__device__ __forceinline__ void mma_comp(const __nv_bfloat16* As, const __nv_bfloat16* Bs,
                                         int mrow0, int ncol0, int grp, int tig,
                                         float (&acc)[2][NT][4]) {
#pragma unroll
    for (int mt = 0; mt < 2; mt++)
#pragma unroll
        for (int nt = 0; nt < NT; nt++)
#pragma unroll
            for (int q = 0; q < 4; q++) acc[mt][nt][q] = 0.f;

    const int segA[3] = {0, 128, 0};
    const int segB[3] = {0, 0, 128};
#pragma unroll
    for (int seg = 0; seg < 3; seg++) {
#pragma unroll
        for (int ks = 0; ks < 8; ks++) {
            int ka = segA[seg] + ks * 16;
            int kb = segB[seg] + ks * 16;
            uint32_t afr[2][4];
#pragma unroll
            for (int mt = 0; mt < 2; mt++) {
                int r = mrow0 + mt * 16 + grp;
                const uint32_t* p0 = reinterpret_cast<const uint32_t*>(&As[r * LDS_K + ka + tig * 2]);
                const uint32_t* p1 = reinterpret_cast<const uint32_t*>(&As[(r + 8) * LDS_K + ka + tig * 2]);
                afr[mt][0] = p0[0];
                afr[mt][1] = p1[0];
                afr[mt][2] = p0[4];
                afr[mt][3] = p1[4];
            }
            uint32_t bfr[NT][2];
#pragma unroll
            for (int nt = 0; nt < NT; nt++) {
                int n = ncol0 + nt * 8 + grp;
                const uint32_t* q = reinterpret_cast<const uint32_t*>(&Bs[n * LDS_K + kb + tig * 2]);
                bfr[nt][0] = q[0];
                bfr[nt][1] = q[4];
            }
#pragma unroll
            for (int mt = 0; mt < 2; mt++)
#pragma unroll
                for (int nt = 0; nt < NT; nt++)
                    asm volatile(
                        "mma.sync.aligned.m16n8k16.row.col.f32.bf16.bf16.f32 "
                        "{%0,%1,%2,%3}, {%4,%5,%6,%7}, {%8,%9}, {%0,%1,%2,%3};"
                        : "+f"(acc[mt][nt][0]), "+f"(acc[mt][nt][1]),
                          "+f"(acc[mt][nt][2]), "+f"(acc[mt][nt][3])
                        : "r"(afr[mt][0]), "r"(afr[mt][1]), "r"(afr[mt][2]), "r"(afr[mt][3]),
                          "r"(bfr[nt][0]), "r"(bfr[nt][1]));
        }
    }
}

// ---------------------------------------------------------------------------
// FUSED GCN: one CTA = 2 samples (100 rows, padded to 128). 3 passes of
//   X = relu(adj @ (X @ Wg^T) + b) entirely in smem.
// 512 threads: GEMM uses 16 warps (4x4 grid, 32x32 warp tiles);
// adj SIMT uses thread = (row-half, sample, dim) with 25 accumulators.
// ---------------------------------------------------------------------------
__global__ void __launch_bounds__(512, 1)
gcn_fused(const float* __restrict__ inputs, const __nv_bfloat16* __restrict__ Wg,
          const float* __restrict__ norm_adj, const float* __restrict__ b_gcn,
          __nv_bfloat16* __restrict__ xs) {
    extern __shared__ __nv_bfloat16 sm[];
    __nv_bfloat16* Xs = sm + FX_OFF;                                   // [128][264]
    __nv_bfloat16* Ws = sm + FW_OFF;                                   // [128][264]
    float* Yf = reinterpret_cast<float*>(reinterpret_cast<char*>(sm) + FYF_BYTE); // [2*52][132]
    float* Af = Yf + FAF_FLT;                                          // [52][52]

    int tid = threadIdx.x;
    int wid = tid >> 5, lane = tid & 31;
    int grp = lane >> 2, tig = lane & 3;
    // GEMM warp grid: 4(m) x 4(n), warp tile 32x32
    int g_mrow0 = (wid & 3) * 32;
    int g_ncol0 = (wid >> 2) * 32;
    // SIMT adj mapping: thread = (row-half, sample, dim); 25 rows each
    int a_half = tid >> 8;            // 0/1
    int a_s    = (tid >> 7) & 1;      // sample
    int a_d    = tid & 127;           // hidden dim
    int a_i0   = a_half * 25;

    size_t m0g = (size_t)blockIdx.x * 100;   // first global row of this CTA

    // --- initial fills ---
    fill_bf16_ca<128, 512>(Ws, Wg, tid);
    {   // X rows 0..99 from inputs (fp32 -> split); rows 100..127 zero
        const float4* g = reinterpret_cast<const float4*>(inputs + m0g * 128);
        for (int i = tid; i < 100 * 32; i += 512) {
            int r = i >> 5, c = i & 31;
            split_store(Xs, r, c, g[r * 32 + c]);
        }
        for (int i = tid; i < 28 * LDS_K / 2; i += 512)
            reinterpret_cast<uint32_t*>(&Xs[100 * LDS_K])[i] = 0;
        // zero all of Yf (covers guard rows 50,51 of each sample)
        for (int i = tid; i < FAF_FLT; i += 512) Yf[i] = 0.f;
    }
    {   // adj [52][52], zero-padded
        for (int i = tid; i < 52 * 52; i += 512) {
            int r = i / 52, c = i - r * 52;
            Af[i] = (r < 50 && c < 50) ? norm_adj[r * 50 + c] : 0.f;
        }
    }
    float bv = b_gcn[a_d];
    CP_COMMIT();
    CP_WAIT0();
    __syncthreads();

    for (int p = 0; p < 3; p++) {
        // ---- Y = X @ Wg^T (tensor cores, compensated) -> Yf fp32 ----
        float acc[2][4][4];
        mma_comp<4>(Xs, Ws, g_mrow0, g_ncol0, grp, tig, acc);

#pragma unroll
        for (int mt = 0; mt < 2; mt++) {
#pragma unroll
            for (int half = 0; half < 2; half++) {
                int rr = g_mrow0 + mt * 16 + grp + half * 8;
                if (rr < 100) {
                    int s = (rr >= 50);
                    int j = rr - s * 50;
                    float* yrow = Yf + (s * 52 + j) * 132;
#pragma unroll
                    for (int nt = 0; nt < 4; nt++) {
                        int c = g_ncol0 + nt * 8 + tig * 2;
                        yrow[c]     = acc[mt][nt][half * 2 + 0];
                        yrow[c + 1] = acc[mt][nt][half * 2 + 1];
                    }
                }
            }
        }
        __syncthreads();

        // ---- X' = relu(adj @ Y + b), SIMT fp32, 25 rows per thread ----
        {
            const float* Ys = Yf + a_s * 52 * 132;
            const float* Ar = Af + a_i0 * 52;
            float ac[25];
#pragma unroll
            for (int i = 0; i < 25; i++) ac[i] = 0.f;

#pragma unroll 1
            for (int j = 0; j < 52; j += 4) {
                float y0 = Ys[(j + 0) * 132 + a_d];
                float y1 = Ys[(j + 1) * 132 + a_d];
                float y2 = Ys[(j + 2) * 132 + a_d];
                float y3 = Ys[(j + 3) * 132 + a_d];
#pragma unroll
                for (int i = 0; i < 25; i++) {
                    float4 a = *reinterpret_cast<const float4*>(&Ar[i * 52 + j]);
                    ac[i] += a.x * y0 + a.y * y1 + a.z * y2 + a.w * y3;
                }
            }
            __syncthreads();   // all reads of Yf done before Xs overwrite races GEMM? (Xs vs Yf disjoint; sync guards Xs rewrite below vs next GEMM)
            if (p < 2) {
#pragma unroll
                for (int i = 0; i < 25; i++) {
                    int row = a_s * 50 + a_i0 + i;
                    float v = fmaxf(ac[i] + bv, 0.f);
                    __nv_bfloat16 h = __float2bfloat16(v);
                    Xs[row * LDS_K + a_d]       = h;
                    Xs[row * LDS_K + 128 + a_d] = __float2bfloat16(v - __bfloat162float(h));
                }
            } else {
#pragma unroll
                for (int i = 0; i < 25; i++) {
                    int row = a_s * 50 + a_i0 + i;
                    float v = fmaxf(ac[i] + bv, 0.f);
                    __nv_bfloat16 h = __float2bfloat16(v);
                    xs[(m0g + row) * 256 + a_d]       = h;
                    xs[(m0g + row) * 256 + 128 + a_d] = __float2bfloat16(v - __bfloat162float(h));
                }
            }
        }
        __syncthreads();
    }
}

// ---------------------------------------------------------------------------
// GEMM: C[M x (nchunks*128)] = A @ W^T (+bias). BM=64, BN=128/chunk.
// 256 thr; warp grid 2(m) x 4(n); warp tile 32x32.  (R8-proven)
// ---------------------------------------------------------------------------
__global__ void __launch_bounds__(256, 2)
gemm_k(const __nv_bfloat16* __restrict__ A, const __nv_bfloat16* __restrict__ W,
       const float* __restrict__ bias, float* __restrict__ out, int ldc, int nchunks) {
    extern __shared__ __nv_bfloat16 sm[];
    __nv_bfloat16* As = sm;
    __nv_bfloat16* Bs = sm + A_TILE;

    int tid = threadIdx.x;
    int wid = tid >> 5, lane = tid & 31;
    int grp = lane >> 2, tig = lane & 3;
    int mrow0 = (wid & 1) * 32;
    int ncol0 = (wid >> 1) * 32;
    size_t m0 = (size_t)blockIdx.x * BM;

    fill_bf16_ca<128, 256>(Bs, W, tid);
    fill_bf16_ca<BM, 256>(As, A + m0 * 256, tid);
    CP_COMMIT();
    CP_WAIT0();
    __syncthreads();

    for (int j = 0; j < nchunks; j++) {
        float acc[2][4][4];
        mma_comp<4>(As, Bs, mrow0, ncol0, grp, tig, acc);

        int cbase = j * 128;
#pragma unroll
        for (int mt = 0; mt < 2; mt++) {
#pragma unroll
            for (int nt = 0; nt < 4; nt++) {
                size_t row = m0 + mrow0 + mt * 16 + grp;
                int col = cbase + ncol0 + nt * 8 + tig * 2;
                float b0 = bias[col], b1 = bias[col + 1];
                float2 v0 = {acc[mt][nt][0] + b0, acc[mt][nt][1] + b1};
                float2 v1 = {acc[mt][nt][2] + b0, acc[mt][nt][3] + b1};
                *reinterpret_cast<float2*>(&out[row * ldc + col]) = v0;
                *reinterpret_cast<float2*>(&out[(row + 8) * ldc + col]) = v1;
            }
        }
        if (j + 1 < nchunks) {
            __syncthreads();
            fill_bf16_ca<128, 256>(Bs, W + (size_t)(j + 1) * 128 * 256, tid);
            CP_COMMIT();
            CP_WAIT0();
            __syncthreads();
        }
    }
}

// ---------------------------------------------------------------------------
// Fused gh GEMM + GRU gates; r and z gates live in registers across chunks.
// (R8-proven)
// ---------------------------------------------------------------------------
__global__ void __launch_bounds__(256, 2)
gemm_gru(const float* __restrict__ hidden, const __nv_bfloat16* __restrict__ W,
         const float* __restrict__ gi, const float* __restrict__ b_hh,
         float* __restrict__ h_out) {
    extern __shared__ __nv_bfloat16 sm[];
    __nv_bfloat16* As = sm;
    __nv_bfloat16* Bs = sm + A_TILE;

    int tid = threadIdx.x;
    int wid = tid >> 5, lane = tid & 31;
    int grp = lane >> 2, tig = lane & 3;
    int mrow0 = (wid & 1) * 32;
    int ncol0 = (wid >> 1) * 32;
    size_t m0 = (size_t)blockIdx.x * BM;

    fill_bf16_ca<128, 256>(Bs, W, tid);
    fill_f32split(As, hidden + m0 * 128, tid);
    CP_COMMIT();
    CP_WAIT0();
    __syncthreads();

    float rreg[2][4][4];
    float zreg[2][4][4];

    for (int j = 0; j < 3; j++) {
        float acc[2][4][4];
        mma_comp<4>(As, Bs, mrow0, ncol0, grp, tig, acc);

#pragma unroll
        for (int mt = 0; mt < 2; mt++) {
#pragma unroll
            for (int nt = 0; nt < 4; nt++) {
                size_t row0 = m0 + mrow0 + mt * 16 + grp;
                int c = ncol0 + nt * 8 + tig * 2;
                float bb0 = b_hh[j * 128 + c], bb1 = b_hh[j * 128 + c + 1];
                float2 gi0 = *reinterpret_cast<const float2*>(&gi[row0 * 384 + j * 128 + c]);
                float2 gi1 = *reinterpret_cast<const float2*>(&gi[(row0 + 8) * 384 + j * 128 + c]);
                float gh00 = acc[mt][nt][0] + bb0, gh01 = acc[mt][nt][1] + bb1;
                float gh10 = acc[mt][nt][2] + bb0, gh11 = acc[mt][nt][3] + bb1;
                if (j == 0) {
                    rreg[mt][nt][0] = 1.f / (1.f + expf(-(gi0.x + gh00)));
                    rreg[mt][nt][1] = 1.f / (1.f + expf(-(gi0.y + gh01)));
                    rreg[mt][nt][2] = 1.f / (1.f + expf(-(gi1.x + gh10)));
                    rreg[mt][nt][3] = 1.f / (1.f + expf(-(gi1.y + gh11)));
                } else if (j == 1) {
                    zreg[mt][nt][0] = 1.f / (1.f + expf(-(gi0.x + gh00)));
                    zreg[mt][nt][1] = 1.f / (1.f + expf(-(gi0.y + gh01)));
                    zreg[mt][nt][2] = 1.f / (1.f + expf(-(gi1.x + gh10)));
                    zreg[mt][nt][3] = 1.f / (1.f + expf(-(gi1.y + gh11)));
                } else {
                    float n00 = tanhf(gi0.x + rreg[mt][nt][0] * gh00);
                    float n01 = tanhf(gi0.y + rreg[mt][nt][1] * gh01);
                    float n10 = tanhf(gi1.x + rreg[mt][nt][2] * gh10);
                    float n11 = tanhf(gi1.y + rreg[mt][nt][3] * gh11);
                    float2 hv0 = *reinterpret_cast<const float2*>(&hidden[row0 * 128 + c]);
                    float2 hv1 = *reinterpret_cast<const float2*>(&hidden[(row0 + 8) * 128 + c]);
                    float z00 = zreg[mt][nt][0], z01 = zreg[mt][nt][1];
                    float z10 = zreg[mt][nt][2], z11 = zreg[mt][nt][3];
                    float2 o0 = {(1.f - z00) * n00 + z00 * hv0.x,
                                 (1.f - z01) * n01 + z01 * hv0.y};
                    float2 o1 = {(1.f - z10) * n10 + z10 * hv1.x,
                                 (1.f - z11) * n11 + z11 * hv1.y};
                    *reinterpret_cast<float2*>(&h_out[row0 * 128 + c]) = o0;
                    *reinterpret_cast<float2*>(&h_out[(row0 + 8) * 128 + c]) = o1;
                }
            }
        }
        if (j < 2) {
            __syncthreads();
            fill_bf16_ca<128, 256>(Bs, W + (size_t)(j + 1) * 128 * 256, tid);
            CP_COMMIT();
            CP_WAIT0();
            __syncthreads();
        }
    }
}

// ---------------------------------------------------------------------------
// fp32 [rows][128] -> bf16 [rows][256] (hi|lo), for weights.
// ---------------------------------------------------------------------------
__global__ void cvt_split(const float* __restrict__ in, __nv_bfloat16* __restrict__ outS,
                          int n4) {
    int i = blockIdx.x * blockDim.x + threadIdx.x;
    if (i >= n4) return;
    float4 v = reinterpret_cast<const float4*>(in)[i];
    int row = i >> 5, c4 = (i & 31) << 2;
    __nv_bfloat16 h0 = __float2bfloat16(v.x), h1 = __float2bfloat16(v.y);
    __nv_bfloat16 h2 = __float2bfloat16(v.z), h3 = __float2bfloat16(v.w);
    __nv_bfloat162 H0{h0, h1}, H1{h2, h3};
    __nv_bfloat162 L0{__float2bfloat16(v.x - __bfloat162float(h0)),
                      __float2bfloat16(v.y - __bfloat162float(h1))};
    __nv_bfloat162 L1{__float2bfloat16(v.z - __bfloat162float(h2)),
                      __float2bfloat16(v.w - __bfloat162float(h3))};
    __nv_bfloat16* base = outS + (size_t)row * 256;
    *reinterpret_cast<__nv_bfloat162*>(base + c4)           = H0;
    *reinterpret_cast<__nv_bfloat162*>(base + c4 + 2)       = H1;
    *reinterpret_cast<__nv_bfloat162*>(base + 128 + c4)     = L0;
    *reinterpret_cast<__nv_bfloat162*>(base + 128 + c4 + 2) = L1;
}

// ---------------------------------------------------------------------------
// q[Mx8] = H[Mx128] @ Wfc2[8x128]^T + b[8]
// ---------------------------------------------------------------------------
__global__ void fc2_kernel(const float* __restrict__ H, const float* __restrict__ W,
                           const float* __restrict__ bias, float* __restrict__ Q) {
    __shared__ float Hs[32][132];
    __shared__ float Ws[8][132];
    int tid = threadIdx.x;
    size_t r0 = (size_t)blockIdx.x * 32;

    for (int i = tid; i < 32 * 32; i += 256) {
        int r = i >> 5, c4 = (i & 31) << 2;
        *(float4*)&Hs[r][c4] = *(const float4*)&H[(r0 + r) * 128 + c4];
    }
    for (int i = tid; i < 8 * 32; i += 256) {
        int r = i >> 5, c4 = (i & 31) << 2;
        *(float4*)&Ws[r][c4] = *(const float4*)&W[r * 128 + c4];
    }
    __syncthreads();

    int rl = tid >> 3, a = tid & 7;
    float acc = 0.f;
#pragma unroll
    for (int k = 0; k < 128; k++) acc += Hs[rl][k] * Ws[a][k];
    Q[(r0 + rl) * 8 + a] = acc + bias[a];
}

// ---------------------------------------------------------------------------
extern "C" void kernel_launch(void* const* d_in, const int* in_sizes, int n_in,
                              void* d_out, int out_size) {
    const float* inputs   = (const float*)d_in[0];
    const float* hidden   = (const float*)d_in[1];
    const float* norm_adj = (const float*)d_in[2];
    const float* w_gcn    = (const float*)d_in[3];
    const float* b_gcn    = (const float*)d_in[4];
    const float* w_ih     = (const float*)d_in[5];
    const float* b_ih     = (const float*)d_in[6];
    const float* w_hh     = (const float*)d_in[7];
    const float* b_hh     = (const float*)d_in[8];
    const float* w_fc2    = (const float*)d_in[9];
    const float* b_fc2    = (const float*)d_in[10];

    float* out = (float*)d_out;
    float* q_out = out;               // (102400, 8)
    float* h_out = out + QSIZE;       // (102400, 128)

    float* gi;
    __nv_bfloat16 *xs, *wgs, *wihs, *whhs;
    cudaGetSymbolAddress((void**)&gi, g_gi);
    cudaGetSymbolAddress((void**)&xs, g_xs);
    cudaGetSymbolAddress((void**)&wgs, g_wgs);
    cudaGetSymbolAddress((void**)&wihs, g_wihs);
    cudaGetSymbolAddress((void**)&whhs, g_whhs);

    cudaFuncSetAttribute(gcn_fused, cudaFuncAttributeMaxDynamicSharedMemorySize, FUSED_SMEM);
    cudaFuncSetAttribute(gemm_k,    cudaFuncAttributeMaxDynamicSharedMemorySize, GEMM_SMEM);
    cudaFuncSetAttribute(gemm_gru,  cudaFuncAttributeMaxDynamicSharedMemorySize, GEMM_SMEM);

    // weight conversions (small)
    cvt_split<<<16, 256>>>(w_gcn, wgs, 128 * 128 / 4);
    cvt_split<<<48, 256>>>(w_ih, wihs, 384 * 128 / 4);
    cvt_split<<<48, 256>>>(w_hh, whhs, 384 * 128 / 4);

    // Fused 3-pass GCN -> xs
    gcn_fused<<<NBATCH / 2, 512, FUSED_SMEM>>>(inputs, wgs, norm_adj, b_gcn, xs);

    // gi = x_c @ w_ih^T + b_ih
    gemm_k<<<NROWS / BM, 256, GEMM_SMEM>>>(xs, wihs, b_ih, gi, 384, 3);
    // gh gemm fused with GRU gates -> h_out
    gemm_gru<<<NROWS / BM, 256, GEMM_SMEM>>>(hidden, whhs, gi, b_hh, h_out);

    // fc2 -> q
    fc2_kernel<<<NROWS / 32, 256>>>(h_out, w_fc2, b_fc2, q_out);
}

// round 12
// speedup vs baseline: 1.1420x; 1.1420x over previous
#include <cuda_runtime.h>
#include <cuda_bf16.h>
#include <cstdint>
#include <math.h>

#define NROWS 102400      // BS * N_AGENTS
#define NBATCH 2048
#define QSIZE (NROWS * 8)

// ---------------- static scratch ----------------
// Split layout: row-major [rows][256] bf16, cols 0..127 = hi, 128..255 = lo.
__device__ __nv_bfloat16  g_xs[NROWS * 256];     // GCN output activations, split
__device__ float          g_gi[NROWS * 384];
__device__ __nv_bfloat16  g_wgs[128 * 256];      // w_gcn split
__device__ __nv_bfloat16  g_wihs[384 * 256];     // w_ih split
__device__ __nv_bfloat16  g_whhs[384 * 256];     // w_hh split
__device__ __nv_bfloat16  g_adjcs[64 * 136];     // adj split [64][hi64|lo64|pad8]

// ---------------- tile geometry ----------------
#define LDS_K 264     // K=256 hi|lo + 8 pad
#define LDS_A 136     // adjC row stride
#define BM 64
#define A_TILE (BM * LDS_K)
#define B_TILE (128 * LDS_K)
#define GEMM_SMEM ((A_TILE + B_TILE) * 2)  // 101376 B

// fused GCN smem (bf16 element offsets):
//   Xs  [128][264] @ 0       rows: s0 j0..49 -> 0..49 (pad 50..63), s1 -> 64..113 (pad 114..127)
//   Ws  [128][264] @ 33792
//   Yt  [128][264] @ 67584   row d, cols: j-hi 0..127 | j-lo 128..255
//   adjC[64][136]  @ 101376
#define GX_OFF 0
#define GW_OFF (128 * LDS_K)
#define GY_OFF (2 * 128 * LDS_K)
#define GA_OFF (3 * 128 * LDS_K)
#define GCN_SMEM ((GA_OFF + 64 * LDS_A) * 2)   // 220160 B

// ---------------- cp.async helpers ----------------
__device__ __forceinline__ uint32_t smem_u32(const void* p) {
    uint32_t a;
    asm("{ .reg .u64 t; cvta.to.shared.u64 t, %1; cvt.u32.u64 %0, t; }" : "=r"(a) : "l"(p));
    return a;
}
#define CP16(dst_u32, src_ptr) \
    asm volatile("cp.async.cg.shared.global [%0], [%1], 16;" :: "r"(dst_u32), "l"(src_ptr))
#define CP_COMMIT()  asm volatile("cp.async.commit_group;" ::: "memory")
#define CP_WAIT0()   asm volatile("cp.async.wait_group 0;" ::: "memory")

template <int ROWS, int NTHR>
__device__ __forceinline__ void fill_bf16_ca(__nv_bfloat16* S, const __nv_bfloat16* G,
                                             int tid) {
    uint32_t sb = smem_u32(S);
    const uint4* g = reinterpret_cast<const uint4*>(G);
    for (int i = tid; i < ROWS * 32; i += NTHR) {
        int r = i >> 5, c = i & 31;
        CP16(sb + (r * LDS_K + c * 8) * 2, g + r * 32 + c);
    }
}
__device__ __forceinline__ void split_store(__nv_bfloat16* S, int r, int c, float4 v) {
    __nv_bfloat16 h0 = __float2bfloat16(v.x), h1 = __float2bfloat16(v.y);
    __nv_bfloat16 h2 = __float2bfloat16(v.z), h3 = __float2bfloat16(v.w);
    __nv_bfloat162 H0{h0, h1}, H1{h2, h3};
    __nv_bfloat162 L0{__float2bfloat16(v.x - __bfloat162float(h0)),
                      __float2bfloat16(v.y - __bfloat162float(h1))};
    __nv_bfloat162 L1{__float2bfloat16(v.z - __bfloat162float(h2)),
                      __float2bfloat16(v.w - __bfloat162float(h3))};
    __nv_bfloat16* hp = &S[r * LDS_K + c * 4];
    __nv_bfloat16* lp = &S[r * LDS_K + 128 + c * 4];
    *reinterpret_cast<__nv_bfloat162*>(hp)     = H0;
    *reinterpret_cast<__nv_bfloat162*>(hp + 2) = H1;
    *reinterpret_cast<__nv_bfloat162*>(lp)     = L0;
    *reinterpret_cast<__nv_bfloat162*>(lp + 2) = L1;
}
__device__ __forceinline__ void fill_f32split(__nv_bfloat16* S, const float* G, int tid) {
    const float4* g = reinterpret_cast<const float4*>(G);
    for (int i = tid; i < BM * 32; i += 256) {
        int r = i >> 5, c = i & 31;
        split_store(S, r, c, g[r * 32 + c]);
    }
}

// ---------------------------------------------------------------------------
// Compensated MMA over [hi|lo] K=256 tiles, stride LDS_K (proven).
// ---------------------------------------------------------------------------
template <int NT>
__device__ __forceinline__ void mma_comp(const __nv_bfloat16* As, const __nv_bfloat16* Bs,
                                         int mrow0, int ncol0, int grp, int tig,
                                         float (&acc)[2][NT][4]) {
#pragma unroll
    for (int mt = 0; mt < 2; mt++)
#pragma unroll
        for (int nt = 0; nt < NT; nt++)
#pragma unroll
            for (int q = 0; q < 4; q++) acc[mt][nt][q] = 0.f;

    const int segA[3] = {0, 128, 0};
    const int segB[3] = {0, 0, 128};
#pragma unroll
    for (int seg = 0; seg < 3; seg++) {
#pragma unroll
        for (int ks = 0; ks < 8; ks++) {
            int ka = segA[seg] + ks * 16;
            int kb = segB[seg] + ks * 16;
            uint32_t afr[2][4];
#pragma unroll
            for (int mt = 0; mt < 2; mt++) {
                int r = mrow0 + mt * 16 + grp;
                const uint32_t* p0 = reinterpret_cast<const uint32_t*>(&As[r * LDS_K + ka + tig * 2]);
                const uint32_t* p1 = reinterpret_cast<const uint32_t*>(&As[(r + 8) * LDS_K + ka + tig * 2]);
                afr[mt][0] = p0[0];
                afr[mt][1] = p1[0];
                afr[mt][2] = p0[4];
                afr[mt][3] = p1[4];
            }
            uint32_t bfr[NT][2];
#pragma unroll
            for (int nt = 0; nt < NT; nt++) {
                int n = ncol0 + nt * 8 + grp;
                const uint32_t* q = reinterpret_cast<const uint32_t*>(&Bs[n * LDS_K + kb + tig * 2]);
                bfr[nt][0] = q[0];
                bfr[nt][1] = q[4];
            }
#pragma unroll
            for (int mt = 0; mt < 2; mt++)
#pragma unroll
                for (int nt = 0; nt < NT; nt++)
                    asm volatile(
                        "mma.sync.aligned.m16n8k16.row.col.f32.bf16.bf16.f32 "
                        "{%0,%1,%2,%3}, {%4,%5,%6,%7}, {%8,%9}, {%0,%1,%2,%3};"
                        : "+f"(acc[mt][nt][0]), "+f"(acc[mt][nt][1]),
                          "+f"(acc[mt][nt][2]), "+f"(acc[mt][nt][3])
                        : "r"(afr[mt][0]), "r"(afr[mt][1]), "r"(afr[mt][2]), "r"(afr[mt][3]),
                          "r"(bfr[nt][0]), "r"(bfr[nt][1]));
        }
    }
}

// Generalized variant: separate A/B strides and per-segment k-offsets (for the
// adj stage: A = adjC [64][136] K=64 segs, B = Yt [128][264] sample window).
template <int LDA, int LDB, int KS, int NT>
__device__ __forceinline__ void mma_comp2(const __nv_bfloat16* As, const __nv_bfloat16* Bs,
                                          const int (&aoff)[3], const int (&boff)[3],
                                          int mrow0, int ncol0, int grp, int tig,
                                          float (&acc)[2][NT][4]) {
#pragma unroll
    for (int mt = 0; mt < 2; mt++)
#pragma unroll
        for (int nt = 0; nt < NT; nt++)
#pragma unroll
            for (int q = 0; q < 4; q++) acc[mt][nt][q] = 0.f;

#pragma unroll
    for (int seg = 0; seg < 3; seg++) {
#pragma unroll
        for (int ks = 0; ks < KS; ks++) {
            int ka = aoff[seg] + ks * 16;
            int kb = boff[seg] + ks * 16;
            uint32_t afr[2][4];
#pragma unroll
            for (int mt = 0; mt < 2; mt++) {
                int r = mrow0 + mt * 16 + grp;
                const uint32_t* p0 = reinterpret_cast<const uint32_t*>(&As[r * LDA + ka + tig * 2]);
                const uint32_t* p1 = reinterpret_cast<const uint32_t*>(&As[(r + 8) * LDA + ka + tig * 2]);
                afr[mt][0] = p0[0];
                afr[mt][1] = p1[0];
                afr[mt][2] = p0[4];
                afr[mt][3] = p1[4];
            }
            uint32_t bfr[NT][2];
#pragma unroll
            for (int nt = 0; nt < NT; nt++) {
                int n = ncol0 + nt * 8 + grp;
                const uint32_t* q = reinterpret_cast<const uint32_t*>(&Bs[n * LDB + kb + tig * 2]);
                bfr[nt][0] = q[0];
                bfr[nt][1] = q[4];
            }
#pragma unroll
            for (int mt = 0; mt < 2; mt++)
#pragma unroll
                for (int nt = 0; nt < NT; nt++)
                    asm volatile(
                        "mma.sync.aligned.m16n8k16.row.col.f32.bf16.bf16.f32 "
                        "{%0,%1,%2,%3}, {%4,%5,%6,%7}, {%8,%9}, {%0,%1,%2,%3};"
                        : "+f"(acc[mt][nt][0]), "+f"(acc[mt][nt][1]),
                          "+f"(acc[mt][nt][2]), "+f"(acc[mt][nt][3])
                        : "r"(afr[mt][0]), "r"(afr[mt][1]), "r"(afr[mt][2]), "r"(afr[mt][3]),
                          "r"(bfr[nt][0]), "r"(bfr[nt][1]));
        }
    }
}

// ---------------------------------------------------------------------------
// FUSED GCN, all tensor-core. One CTA = 2 samples, padded to 64 rows each in
// Xs (s0 -> rows 0..49, s1 -> rows 64..113; pads zero).
// Pass p:
//   phase1: Yt[d][j] = sum_k W[d,k] X[j,k]   (mma_comp, As=Ws, Bs=Xs)
//   phase2: X'[i,d]  = relu(sum_j adjC[i,j] Yt[d][j] + b)  (mma_comp2, per-sample)
// 512 threads, 1 CTA/SM, grid = NBATCH/2.
// ---------------------------------------------------------------------------
__global__ void __launch_bounds__(512, 1)
gcn_fused(const float* __restrict__ inputs, const __nv_bfloat16* __restrict__ Wg,
          const __nv_bfloat16* __restrict__ adjcs, const float* __restrict__ b_gcn,
          __nv_bfloat16* __restrict__ xs) {
    extern __shared__ __nv_bfloat16 sm[];
    __nv_bfloat16* Xs   = sm + GX_OFF;   // [128][264]
    __nv_bfloat16* Ws   = sm + GW_OFF;   // [128][264]
    __nv_bfloat16* Yt   = sm + GY_OFF;   // [128][264]
    __nv_bfloat16* adjC = sm + GA_OFF;   // [64][136]

    int tid = threadIdx.x;
    int wid = tid >> 5, lane = tid & 31;
    int grp = lane >> 2, tig = lane & 3;
    // phase1 warp grid: 4(m=d) x 4(n=j), warp tile 32x32
    int g_mrow0 = (wid & 3) * 32;
    int g_ncol0 = (wid >> 2) * 32;
    // phase2: sample = wid>>3; within: 2(m=i) x 4(n=d), warp tile 32x32
    int a_s     = wid >> 3;
    int aw      = wid & 7;
    int a_mrow0 = (aw & 1) * 32;
    int a_ncol0 = (aw >> 1) * 32;

    size_t m0g = (size_t)blockIdx.x * 100;   // first global row of this CTA

    // --- initial fills ---
    fill_bf16_ca<128, 512>(Ws, Wg, tid);
    {   // adjC: 64*136 bf16 = 1088 uint4
        uint32_t sb = smem_u32(adjC);
        const uint4* g = reinterpret_cast<const uint4*>(adjcs);
        for (int i = tid; i < 1088; i += 512) CP16(sb + i * 16, g + i);
    }
    {   // X: global row g (0..99) -> local row (g/50)*64 + g%50, fp32 -> split
        const float4* g4 = reinterpret_cast<const float4*>(inputs + m0g * 128);
        for (int i = tid; i < 100 * 32; i += 512) {
            int g = i >> 5, c = i & 31;
            int s = (g >= 50);
            int lr = s * 64 + (g - s * 50);
            split_store(Xs, lr, c, g4[g * 32 + c]);
        }
        // zero pad rows 50..63 and 114..127 (full 264-elem rows)
        for (int i = tid; i < 28 * 132; i += 512) {
            int r = i / 132, c = i - (i / 132) * 132;
            int rr = (r < 14) ? (50 + r) : (114 + r - 14);
            reinterpret_cast<uint32_t*>(&Xs[rr * LDS_K])[c] = 0;
        }
    }
    // bias regs for phase2 epilogue (d fixed per thread)
    float bb[4][2];
#pragma unroll
    for (int nt = 0; nt < 4; nt++) {
        int d = a_ncol0 + nt * 8 + tig * 2;
        bb[nt][0] = b_gcn[d];
        bb[nt][1] = b_gcn[d + 1];
    }
    const int aoffs[3] = {0, 64, 0};
    const int boffs[3] = {a_s * 64, a_s * 64, 128 + a_s * 64};

    CP_COMMIT();
    CP_WAIT0();
    __syncthreads();

    for (int p = 0; p < 3; p++) {
        // ---- phase1: Yt = W @ X^T (covers all 128x128, pads give zeros) ----
        {
            float acc[2][4][4];
            mma_comp<4>(Ws, Xs, g_mrow0, g_ncol0, grp, tig, acc);
#pragma unroll
            for (int mt = 0; mt < 2; mt++) {
#pragma unroll
                for (int half = 0; half < 2; half++) {
                    int d = g_mrow0 + mt * 16 + grp + half * 8;
                    __nv_bfloat16* yrow = Yt + d * LDS_K;
#pragma unroll
                    for (int nt = 0; nt < 4; nt++) {
                        int j = g_ncol0 + nt * 8 + tig * 2;
                        float v0 = acc[mt][nt][half * 2 + 0];
                        float v1 = acc[mt][nt][half * 2 + 1];
                        __nv_bfloat16 h0 = __float2bfloat16(v0);
                        __nv_bfloat16 h1 = __float2bfloat16(v1);
                        *reinterpret_cast<__nv_bfloat162*>(yrow + j) = __nv_bfloat162{h0, h1};
                        *reinterpret_cast<__nv_bfloat162*>(yrow + 128 + j) =
                            __nv_bfloat162{__float2bfloat16(v0 - __bfloat162float(h0)),
                                           __float2bfloat16(v1 - __bfloat162float(h1))};
                    }
                }
            }
        }
        __syncthreads();

        // ---- phase2: X' = relu(adj @ Y + b), per-sample windows ----
        {
            float acc[2][4][4];
            mma_comp2<LDS_A, LDS_K, 4, 4>(adjC, Yt, aoffs, boffs,
                                          a_mrow0, a_ncol0, grp, tig, acc);
#pragma unroll
            for (int mt = 0; mt < 2; mt++) {
#pragma unroll
                for (int half = 0; half < 2; half++) {
                    int i_loc = a_mrow0 + mt * 16 + grp + half * 8;   // 0..63
                    if (i_loc < 50) {
#pragma unroll
                        for (int nt = 0; nt < 4; nt++) {
                            int d = a_ncol0 + nt * 8 + tig * 2;
                            float v0 = fmaxf(acc[mt][nt][half * 2 + 0] + bb[nt][0], 0.f);
                            float v1 = fmaxf(acc[mt][nt][half * 2 + 1] + bb[nt][1], 0.f);
                            __nv_bfloat16 h0 = __float2bfloat16(v0);
                            __nv_bfloat16 h1 = __float2bfloat16(v1);
                            __nv_bfloat162 H{h0, h1};
                            __nv_bfloat162 L{__float2bfloat16(v0 - __bfloat162float(h0)),
                                             __float2bfloat16(v1 - __bfloat162float(h1))};
                            if (p < 2) {
                                __nv_bfloat16* xrow = Xs + (a_s * 64 + i_loc) * LDS_K;
                                *reinterpret_cast<__nv_bfloat162*>(xrow + d)       = H;
                                *reinterpret_cast<__nv_bfloat162*>(xrow + 128 + d) = L;
                            } else {
                                __nv_bfloat16* xrow = xs + (m0g + a_s * 50 + i_loc) * 256;
                                *reinterpret_cast<__nv_bfloat162*>(xrow + d)       = H;
                                *reinterpret_cast<__nv_bfloat162*>(xrow + 128 + d) = L;
                            }
                        }
                    }
                }
            }
        }
        __syncthreads();
    }
}

// ---------------------------------------------------------------------------
// GEMM: C[M x (nchunks*128)] = A @ W^T (+bias). BM=64, BN=128/chunk. (R8-proven)
// ---------------------------------------------------------------------------
__global__ void __launch_bounds__(256, 2)
gemm_k(const __nv_bfloat16* __restrict__ A, const __nv_bfloat16* __restrict__ W,
       const float* __restrict__ bias, float* __restrict__ out, int ldc, int nchunks) {
    extern __shared__ __nv_bfloat16 sm[];
    __nv_bfloat16* As = sm;
    __nv_bfloat16* Bs = sm + A_TILE;

    int tid = threadIdx.x;
    int wid = tid >> 5, lane = tid & 31;
    int grp = lane >> 2, tig = lane & 3;
    int mrow0 = (wid & 1) * 32;
    int ncol0 = (wid >> 1) * 32;
    size_t m0 = (size_t)blockIdx.x * BM;

    fill_bf16_ca<128, 256>(Bs, W, tid);
    fill_bf16_ca<BM, 256>(As, A + m0 * 256, tid);
    CP_COMMIT();
    CP_WAIT0();
    __syncthreads();

    for (int j = 0; j < nchunks; j++) {
        float acc[2][4][4];
        mma_comp<4>(As, Bs, mrow0, ncol0, grp, tig, acc);

        int cbase = j * 128;
#pragma unroll
        for (int mt = 0; mt < 2; mt++) {
#pragma unroll
            for (int nt = 0; nt < 4; nt++) {
                size_t row = m0 + mrow0 + mt * 16 + grp;
                int col = cbase + ncol0 + nt * 8 + tig * 2;
                float b0 = bias[col], b1 = bias[col + 1];
                float2 v0 = {acc[mt][nt][0] + b0, acc[mt][nt][1] + b1};
                float2 v1 = {acc[mt][nt][2] + b0, acc[mt][nt][3] + b1};
                *reinterpret_cast<float2*>(&out[row * ldc + col]) = v0;
                *reinterpret_cast<float2*>(&out[(row + 8) * ldc + col]) = v1;
            }
        }
        if (j + 1 < nchunks) {
            __syncthreads();
            fill_bf16_ca<128, 256>(Bs, W + (size_t)(j + 1) * 128 * 256, tid);
            CP_COMMIT();
            CP_WAIT0();
            __syncthreads();
        }
    }
}

// ---------------------------------------------------------------------------
// Fused gh GEMM + GRU gates; r and z gates live in registers. (R8-proven)
// ---------------------------------------------------------------------------
__global__ void __launch_bounds__(256, 2)
gemm_gru(const float* __restrict__ hidden, const __nv_bfloat16* __restrict__ W,
         const float* __restrict__ gi, const float* __restrict__ b_hh,
         float* __restrict__ h_out) {
    extern __shared__ __nv_bfloat16 sm[];
    __nv_bfloat16* As = sm;
    __nv_bfloat16* Bs = sm + A_TILE;

    int tid = threadIdx.x;
    int wid = tid >> 5, lane = tid & 31;
    int grp = lane >> 2, tig = lane & 3;
    int mrow0 = (wid & 1) * 32;
    int ncol0 = (wid >> 1) * 32;
    size_t m0 = (size_t)blockIdx.x * BM;

    fill_bf16_ca<128, 256>(Bs, W, tid);
    fill_f32split(As, hidden + m0 * 128, tid);
    CP_COMMIT();
    CP_WAIT0();
    __syncthreads();

    float rreg[2][4][4];
    float zreg[2][4][4];

    for (int j = 0; j < 3; j++) {
        float acc[2][4][4];
        mma_comp<4>(As, Bs, mrow0, ncol0, grp, tig, acc);

#pragma unroll
        for (int mt = 0; mt < 2; mt++) {
#pragma unroll
            for (int nt = 0; nt < 4; nt++) {
                size_t row0 = m0 + mrow0 + mt * 16 + grp;
                int c = ncol0 + nt * 8 + tig * 2;
                float bb0 = b_hh[j * 128 + c], bb1 = b_hh[j * 128 + c + 1];
                float2 gi0 = *reinterpret_cast<const float2*>(&gi[row0 * 384 + j * 128 + c]);
                float2 gi1 = *reinterpret_cast<const float2*>(&gi[(row0 + 8) * 384 + j * 128 + c]);
                float gh00 = acc[mt][nt][0] + bb0, gh01 = acc[mt][nt][1] + bb1;
                float gh10 = acc[mt][nt][2] + bb0, gh11 = acc[mt][nt][3] + bb1;
                if (j == 0) {
                    rreg[mt][nt][0] = 1.f / (1.f + expf(-(gi0.x + gh00)));
                    rreg[mt][nt][1] = 1.f / (1.f + expf(-(gi0.y + gh01)));
                    rreg[mt][nt][2] = 1.f / (1.f + expf(-(gi1.x + gh10)));
                    rreg[mt][nt][3] = 1.f / (1.f + expf(-(gi1.y + gh11)));
                } else if (j == 1) {
                    zreg[mt][nt][0] = 1.f / (1.f + expf(-(gi0.x + gh00)));
                    zreg[mt][nt][1] = 1.f / (1.f + expf(-(gi0.y + gh01)));
                    zreg[mt][nt][2] = 1.f / (1.f + expf(-(gi1.x + gh10)));
                    zreg[mt][nt][3] = 1.f / (1.f + expf(-(gi1.y + gh11)));
                } else {
                    float n00 = tanhf(gi0.x + rreg[mt][nt][0] * gh00);
                    float n01 = tanhf(gi0.y + rreg[mt][nt][1] * gh01);
                    float n10 = tanhf(gi1.x + rreg[mt][nt][2] * gh10);
                    float n11 = tanhf(gi1.y + rreg[mt][nt][3] * gh11);
                    float2 hv0 = *reinterpret_cast<const float2*>(&hidden[row0 * 128 + c]);
                    float2 hv1 = *reinterpret_cast<const float2*>(&hidden[(row0 + 8) * 128 + c]);
                    float z00 = zreg[mt][nt][0], z01 = zreg[mt][nt][1];
                    float z10 = zreg[mt][nt][2], z11 = zreg[mt][nt][3];
                    float2 o0 = {(1.f - z00) * n00 + z00 * hv0.x,
                                 (1.f - z01) * n01 + z01 * hv0.y};
                    float2 o1 = {(1.f - z10) * n10 + z10 * hv1.x,
                                 (1.f - z11) * n11 + z11 * hv1.y};
                    *reinterpret_cast<float2*>(&h_out[row0 * 128 + c]) = o0;
                    *reinterpret_cast<float2*>(&h_out[(row0 + 8) * 128 + c]) = o1;
                }
            }
        }
        if (j < 2) {
            __syncthreads();
            fill_bf16_ca<128, 256>(Bs, W + (size_t)(j + 1) * 128 * 256, tid);
            CP_COMMIT();
            CP_WAIT0();
            __syncthreads();
        }
    }
}

// ---------------------------------------------------------------------------
// fp32 [rows][128] -> bf16 [rows][256] (hi|lo), for weights.
// ---------------------------------------------------------------------------
__global__ void cvt_split(const float* __restrict__ in, __nv_bfloat16* __restrict__ outS,
                          int n4) {
    int i = blockIdx.x * blockDim.x + threadIdx.x;
    if (i >= n4) return;
    float4 v = reinterpret_cast<const float4*>(in)[i];
    int row = i >> 5, c4 = (i & 31) << 2;
    __nv_bfloat16 h0 = __float2bfloat16(v.x), h1 = __float2bfloat16(v.y);
    __nv_bfloat16 h2 = __float2bfloat16(v.z), h3 = __float2bfloat16(v.w);
    __nv_bfloat162 H0{h0, h1}, H1{h2, h3};
    __nv_bfloat162 L0{__float2bfloat16(v.x - __bfloat162float(h0)),
                      __float2bfloat16(v.y - __bfloat162float(h1))};
    __nv_bfloat162 L1{__float2bfloat16(v.z - __bfloat162float(h2)),
                      __float2bfloat16(v.w - __bfloat162float(h3))};
    __nv_bfloat16* base = outS + (size_t)row * 256;
    *reinterpret_cast<__nv_bfloat162*>(base + c4)           = H0;
    *reinterpret_cast<__nv_bfloat162*>(base + c4 + 2)       = H1;
    *reinterpret_cast<__nv_bfloat162*>(base + 128 + c4)     = L0;
    *reinterpret_cast<__nv_bfloat162*>(base + 128 + c4 + 2) = L1;
}

// norm_adj (50x50 fp32) -> adjcs [64][136]: cols 0..63 hi(adj[r][j]), 64..127 lo, pad 0.
__global__ void adjc_split(const float* __restrict__ adj, __nv_bfloat16* __restrict__ out) {
    for (int idx = threadIdx.x; idx < 64 * 136; idx += 256) {
        int r = idx / 136, k = idx - (idx / 136) * 136;
        int j = (k < 64) ? k : k - 64;
        float v = (k < 128 && r < 50 && j < 50) ? adj[r * 50 + j] : 0.f;
        __nv_bfloat16 h = __float2bfloat16(v);
        out[idx] = (k < 64) ? h : __float2bfloat16(v - __bfloat162float(h));
    }
}

// ---------------------------------------------------------------------------
// q[Mx8] = H[Mx128] @ Wfc2[8x128]^T + b[8]
// ---------------------------------------------------------------------------
__global__ void fc2_kernel(const float* __restrict__ H, const float* __restrict__ W,
                           const float* __restrict__ bias, float* __restrict__ Q) {
    __shared__ float Hs[32][132];
    __shared__ float Ws[8][132];
    int tid = threadIdx.x;
    size_t r0 = (size_t)blockIdx.x * 32;

    for (int i = tid; i < 32 * 32; i += 256) {
        int r = i >> 5, c4 = (i & 31) << 2;
        *(float4*)&Hs[r][c4] = *(const float4*)&H[(r0 + r) * 128 + c4];
    }
    for (int i = tid; i < 8 * 32; i += 256) {
        int r = i >> 5, c4 = (i & 31) << 2;
        *(float4*)&Ws[r][c4] = *(const float4*)&W[r * 128 + c4];
    }
    __syncthreads();

    int rl = tid >> 3, a = tid & 7;
    float acc = 0.f;
#pragma unroll
    for (int k = 0; k < 128; k++) acc += Hs[rl][k] * Ws[a][k];
    Q[(r0 + rl) * 8 + a] = acc + bias[a];
}

// ---------------------------------------------------------------------------
extern "C" void kernel_launch(void* const* d_in, const int* in_sizes, int n_in,
                              void* d_out, int out_size) {
    const float* inputs   = (const float*)d_in[0];
    const float* hidden   = (const float*)d_in[1];
    const float* norm_adj = (const float*)d_in[2];
    const float* w_gcn    = (const float*)d_in[3];
    const float* b_gcn    = (const float*)d_in[4];
    const float* w_ih     = (const float*)d_in[5];
    const float* b_ih     = (const float*)d_in[6];
    const float* w_hh     = (const float*)d_in[7];
    const float* b_hh     = (const float*)d_in[8];
    const float* w_fc2    = (const float*)d_in[9];
    const float* b_fc2    = (const float*)d_in[10];

    float* out = (float*)d_out;
    float* q_out = out;               // (102400, 8)
    float* h_out = out + QSIZE;       // (102400, 128)

    float* gi;
    __nv_bfloat16 *xs, *wgs, *wihs, *whhs, *adjcs;
    cudaGetSymbolAddress((void**)&gi, g_gi);
    cudaGetSymbolAddress((void**)&xs, g_xs);
    cudaGetSymbolAddress((void**)&wgs, g_wgs);
    cudaGetSymbolAddress((void**)&wihs, g_wihs);
    cudaGetSymbolAddress((void**)&whhs, g_whhs);
    cudaGetSymbolAddress((void**)&adjcs, g_adjcs);

    cudaFuncSetAttribute(gcn_fused, cudaFuncAttributeMaxDynamicSharedMemorySize, GCN_SMEM);
    cudaFuncSetAttribute(gemm_k,    cudaFuncAttributeMaxDynamicSharedMemorySize, GEMM_SMEM);
    cudaFuncSetAttribute(gemm_gru,  cudaFuncAttributeMaxDynamicSharedMemorySize, GEMM_SMEM);

    // weight/adj conversions (small)
    cvt_split<<<16, 256>>>(w_gcn, wgs, 128 * 128 / 4);
    cvt_split<<<48, 256>>>(w_ih, wihs, 384 * 128 / 4);
    cvt_split<<<48, 256>>>(w_hh, whhs, 384 * 128 / 4);
    adjc_split<<<1, 256>>>(norm_adj, adjcs);

    // Fused 3-pass GCN -> xs (all tensor-core)
    gcn_fused<<<NBATCH / 2, 512, GCN_SMEM>>>(inputs, wgs, adjcs, b_gcn, xs);

    // gi = x_c @ w_ih^T + b_ih
    gemm_k<<<NROWS / BM, 256, GEMM_SMEM>>>(xs, wihs, b_ih, gi, 384, 3);
    // gh gemm fused with GRU gates -> h_out
    gemm_gru<<<NROWS / BM, 256, GEMM_SMEM>>>(hidden, whhs, gi, b_hh, h_out);

    // fc2 -> q
    fc2_kernel<<<NROWS / 32, 256>>>(h_out, w_fc2, b_fc2, q_out);
}

// round 13
// speedup vs baseline: 1.1803x; 1.0335x over previous
#include <cuda_runtime.h>
#include <cuda_bf16.h>
#include <cstdint>
#include <math.h>

#define NROWS 102400      // BS * N_AGENTS
#define NBATCH 2048
#define QSIZE (NROWS * 8)

// ---------------- static scratch ----------------
__device__ float          g_gi[NROWS * 384];
__device__ __nv_bfloat16  g_wgs[128 * 256];      // w_gcn split
__device__ __nv_bfloat16  g_wihs[384 * 256];     // w_ih split
__device__ __nv_bfloat16  g_whhs[384 * 256];     // w_hh split
__device__ __nv_bfloat16  g_adjcs[64 * 136];     // adj split [64][hi64|lo64|pad8]

// ---------------- tile geometry ----------------
#define LDS_K 264     // K=256 hi|lo + 8 pad
#define LDS_A 136     // adjC row stride
#define BM 64
#define A_TILE (BM * LDS_K)
#define B_TILE (128 * LDS_K)
#define GEMM_SMEM ((A_TILE + B_TILE) * 2)  // 101376 B

// fused GCN smem (bf16 element offsets)
#define GX_OFF 0
#define GW_OFF (128 * LDS_K)
#define GY_OFF (2 * 128 * LDS_K)
#define GA_OFF (3 * 128 * LDS_K)
#define GCN_SMEM ((GA_OFF + 64 * LDS_A) * 2)   // 220160 B

// ---------------- cp.async helpers ----------------
__device__ __forceinline__ uint32_t smem_u32(const void* p) {
    uint32_t a;
    asm("{ .reg .u64 t; cvta.to.shared.u64 t, %1; cvt.u32.u64 %0, t; }" : "=r"(a) : "l"(p));
    return a;
}
#define CP16(dst_u32, src_ptr) \
    asm volatile("cp.async.cg.shared.global [%0], [%1], 16;" :: "r"(dst_u32), "l"(src_ptr))
#define CP_COMMIT()  asm volatile("cp.async.commit_group;" ::: "memory")
#define CP_WAIT0()   asm volatile("cp.async.wait_group 0;" ::: "memory")

template <int ROWS, int NTHR>
__device__ __forceinline__ void fill_bf16_ca(__nv_bfloat16* S, const __nv_bfloat16* G,
                                             int tid) {
    uint32_t sb = smem_u32(S);
    const uint4* g = reinterpret_cast<const uint4*>(G);
    for (int i = tid; i < ROWS * 32; i += NTHR) {
        int r = i >> 5, c = i & 31;
        CP16(sb + (r * LDS_K + c * 8) * 2, g + r * 32 + c);
    }
}
__device__ __forceinline__ void split_store(__nv_bfloat16* S, int r, int c, float4 v) {
    __nv_bfloat16 h0 = __float2bfloat16(v.x), h1 = __float2bfloat16(v.y);
    __nv_bfloat16 h2 = __float2bfloat16(v.z), h3 = __float2bfloat16(v.w);
    __nv_bfloat162 H0{h0, h1}, H1{h2, h3};
    __nv_bfloat162 L0{__float2bfloat16(v.x - __bfloat162float(h0)),
                      __float2bfloat16(v.y - __bfloat162float(h1))};
    __nv_bfloat162 L1{__float2bfloat16(v.z - __bfloat162float(h2)),
                      __float2bfloat16(v.w - __bfloat162float(h3))};
    __nv_bfloat16* hp = &S[r * LDS_K + c * 4];
    __nv_bfloat16* lp = &S[r * LDS_K + 128 + c * 4];
    *reinterpret_cast<__nv_bfloat162*>(hp)     = H0;
    *reinterpret_cast<__nv_bfloat162*>(hp + 2) = H1;
    *reinterpret_cast<__nv_bfloat162*>(lp)     = L0;
    *reinterpret_cast<__nv_bfloat162*>(lp + 2) = L1;
}
__device__ __forceinline__ void fill_f32split(__nv_bfloat16* S, const float* G, int tid) {
    const float4* g = reinterpret_cast<const float4*>(G);
    for (int i = tid; i < BM * 32; i += 256) {
        int r = i >> 5, c = i & 31;
        split_store(S, r, c, g[r * 32 + c]);
    }
}

// ---------------------------------------------------------------------------
// Compensated MMA over [hi|lo] K=256 tiles, stride LDS_K (proven).
// ---------------------------------------------------------------------------
template <int NT>
__device__ __forceinline__ void mma_comp(const __nv_bfloat16* As, const __nv_bfloat16* Bs,
                                         int mrow0, int ncol0, int grp, int tig,
                                         float (&acc)[2][NT][4]) {
#pragma unroll
    for (int mt = 0; mt < 2; mt++)
#pragma unroll
        for (int nt = 0; nt < NT; nt++)
#pragma unroll
            for (int q = 0; q < 4; q++) acc[mt][nt][q] = 0.f;

    const int segA[3] = {0, 128, 0};
    const int segB[3] = {0, 0, 128};
#pragma unroll
    for (int seg = 0; seg < 3; seg++) {
#pragma unroll
        for (int ks = 0; ks < 8; ks++) {
            int ka = segA[seg] + ks * 16;
            int kb = segB[seg] + ks * 16;
            uint32_t afr[2][4];
#pragma unroll
            for (int mt = 0; mt < 2; mt++) {
                int r = mrow0 + mt * 16 + grp;
                const uint32_t* p0 = reinterpret_cast<const uint32_t*>(&As[r * LDS_K + ka + tig * 2]);
                const uint32_t* p1 = reinterpret_cast<const uint32_t*>(&As[(r + 8) * LDS_K + ka + tig * 2]);
                afr[mt][0] = p0[0];
                afr[mt][1] = p1[0];
                afr[mt][2] = p0[4];
                afr[mt][3] = p1[4];
            }
            uint32_t bfr[NT][2];
#pragma unroll
            for (int nt = 0; nt < NT; nt++) {
                int n = ncol0 + nt * 8 + grp;
                const uint32_t* q = reinterpret_cast<const uint32_t*>(&Bs[n * LDS_K + kb + tig * 2]);
                bfr[nt][0] = q[0];
                bfr[nt][1] = q[4];
            }
#pragma unroll
            for (int mt = 0; mt < 2; mt++)
#pragma unroll
                for (int nt = 0; nt < NT; nt++)
                    asm volatile(
                        "mma.sync.aligned.m16n8k16.row.col.f32.bf16.bf16.f32 "
                        "{%0,%1,%2,%3}, {%4,%5,%6,%7}, {%8,%9}, {%0,%1,%2,%3};"
                        : "+f"(acc[mt][nt][0]), "+f"(acc[mt][nt][1]),
                          "+f"(acc[mt][nt][2]), "+f"(acc[mt][nt][3])
                        : "r"(afr[mt][0]), "r"(afr[mt][1]), "r"(afr[mt][2]), "r"(afr[mt][3]),
                          "r"(bfr[nt][0]), "r"(bfr[nt][1]));
        }
    }
}

// Generalized: separate A/B strides and per-segment k-offsets (adj stage).
template <int LDA, int LDB, int KS, int NT>
__device__ __forceinline__ void mma_comp2(const __nv_bfloat16* As, const __nv_bfloat16* Bs,
                                          const int (&aoff)[3], const int (&boff)[3],
                                          int mrow0, int ncol0, int grp, int tig,
                                          float (&acc)[2][NT][4]) {
#pragma unroll
    for (int mt = 0; mt < 2; mt++)
#pragma unroll
        for (int nt = 0; nt < NT; nt++)
#pragma unroll
            for (int q = 0; q < 4; q++) acc[mt][nt][q] = 0.f;

#pragma unroll
    for (int seg = 0; seg < 3; seg++) {
#pragma unroll
        for (int ks = 0; ks < KS; ks++) {
            int ka = aoff[seg] + ks * 16;
            int kb = boff[seg] + ks * 16;
            uint32_t afr[2][4];
#pragma unroll
            for (int mt = 0; mt < 2; mt++) {
                int r = mrow0 + mt * 16 + grp;
                const uint32_t* p0 = reinterpret_cast<const uint32_t*>(&As[r * LDA + ka + tig * 2]);
                const uint32_t* p1 = reinterpret_cast<const uint32_t*>(&As[(r + 8) * LDA + ka + tig * 2]);
                afr[mt][0] = p0[0];
                afr[mt][1] = p1[0];
                afr[mt][2] = p0[4];
                afr[mt][3] = p1[4];
            }
            uint32_t bfr[NT][2];
#pragma unroll
            for (int nt = 0; nt < NT; nt++) {
                int n = ncol0 + nt * 8 + grp;
                const uint32_t* q = reinterpret_cast<const uint32_t*>(&Bs[n * LDB + kb + tig * 2]);
                bfr[nt][0] = q[0];
                bfr[nt][1] = q[4];
            }
#pragma unroll
            for (int mt = 0; mt < 2; mt++)
#pragma unroll
                for (int nt = 0; nt < NT; nt++)
                    asm volatile(
                        "mma.sync.aligned.m16n8k16.row.col.f32.bf16.bf16.f32 "
                        "{%0,%1,%2,%3}, {%4,%5,%6,%7}, {%8,%9}, {%0,%1,%2,%3};"
                        : "+f"(acc[mt][nt][0]), "+f"(acc[mt][nt][1]),
                          "+f"(acc[mt][nt][2]), "+f"(acc[mt][nt][3])
                        : "r"(afr[mt][0]), "r"(afr[mt][1]), "r"(afr[mt][2]), "r"(afr[mt][3]),
                          "r"(bfr[nt][0]), "r"(bfr[nt][1]));
        }
    }
}

// ---------------------------------------------------------------------------
// FUSED GCN + gi GEMM. One CTA = 2 samples (rows 0..49, 64..113 in Xs; pads 0).
// 3 passes of X = relu(adj @ (X @ Wg^T) + b), all tensor-core, then
// gi = X @ w_ih^T + b_ih computed from the smem-resident X (3 weight chunks
// rotated through the Ws buffer). No xs global round-trip.
// 512 threads, 1 CTA/SM, grid = NBATCH/2.
// ---------------------------------------------------------------------------
__global__ void __launch_bounds__(512, 1)
gcn_fused(const float* __restrict__ inputs, const __nv_bfloat16* __restrict__ Wg,
          const __nv_bfloat16* __restrict__ wihs, const __nv_bfloat16* __restrict__ adjcs,
          const float* __restrict__ b_gcn, const float* __restrict__ b_ih,
          float* __restrict__ gi) {
    extern __shared__ __nv_bfloat16 sm[];
    __nv_bfloat16* Xs   = sm + GX_OFF;   // [128][264]
    __nv_bfloat16* Ws   = sm + GW_OFF;   // [128][264]
    __nv_bfloat16* Yt   = sm + GY_OFF;   // [128][264]
    __nv_bfloat16* adjC = sm + GA_OFF;   // [64][136]

    int tid = threadIdx.x;
    int wid = tid >> 5, lane = tid & 31;
    int grp = lane >> 2, tig = lane & 3;
    int g_mrow0 = (wid & 3) * 32;
    int g_ncol0 = (wid >> 2) * 32;
    int a_s     = wid >> 3;
    int aw      = wid & 7;
    int a_mrow0 = (aw & 1) * 32;
    int a_ncol0 = (aw >> 1) * 32;

    size_t m0g = (size_t)blockIdx.x * 100;

    // --- initial fills ---
    fill_bf16_ca<128, 512>(Ws, Wg, tid);
    {   // adjC: 1088 uint4
        uint32_t sb = smem_u32(adjC);
        const uint4* g = reinterpret_cast<const uint4*>(adjcs);
        for (int i = tid; i < 1088; i += 512) CP16(sb + i * 16, g + i);
    }
    {   // X rows: global g (0..99) -> local (g/50)*64 + g%50
        const float4* g4 = reinterpret_cast<const float4*>(inputs + m0g * 128);
        for (int i = tid; i < 100 * 32; i += 512) {
            int g = i >> 5, c = i & 31;
            int s = (g >= 50);
            split_store(Xs, s * 64 + (g - s * 50), c, g4[g * 32 + c]);
        }
        for (int i = tid; i < 28 * 132; i += 512) {
            int r = i / 132, c = i - (i / 132) * 132;
            int rr = (r < 14) ? (50 + r) : (114 + r - 14);
            reinterpret_cast<uint32_t*>(&Xs[rr * LDS_K])[c] = 0;
        }
    }
    float bb[4][2];
#pragma unroll
    for (int nt = 0; nt < 4; nt++) {
        int d = a_ncol0 + nt * 8 + tig * 2;
        bb[nt][0] = b_gcn[d];
        bb[nt][1] = b_gcn[d + 1];
    }
    const int aoffs[3] = {0, 64, 0};
    const int boffs[3] = {a_s * 64, a_s * 64, 128 + a_s * 64};

    CP_COMMIT();
    CP_WAIT0();
    __syncthreads();

    for (int p = 0; p < 3; p++) {
        // phase1: Yt[d][j] = sum_k W[d,k] X[j,k]
        {
            float acc[2][4][4];
            mma_comp<4>(Ws, Xs, g_mrow0, g_ncol0, grp, tig, acc);
#pragma unroll
            for (int mt = 0; mt < 2; mt++) {
#pragma unroll
                for (int half = 0; half < 2; half++) {
                    int d = g_mrow0 + mt * 16 + grp + half * 8;
                    __nv_bfloat16* yrow = Yt + d * LDS_K;
#pragma unroll
                    for (int nt = 0; nt < 4; nt++) {
                        int j = g_ncol0 + nt * 8 + tig * 2;
                        float v0 = acc[mt][nt][half * 2 + 0];
                        float v1 = acc[mt][nt][half * 2 + 1];
                        __nv_bfloat16 h0 = __float2bfloat16(v0);
                        __nv_bfloat16 h1 = __float2bfloat16(v1);
                        *reinterpret_cast<__nv_bfloat162*>(yrow + j) = __nv_bfloat162{h0, h1};
                        *reinterpret_cast<__nv_bfloat162*>(yrow + 128 + j) =
                            __nv_bfloat162{__float2bfloat16(v0 - __bfloat162float(h0)),
                                           __float2bfloat16(v1 - __bfloat162float(h1))};
                    }
                }
            }
        }
        __syncthreads();

        // phase2: X' = relu(adj @ Y + b) -> back into Xs (all 3 passes)
        {
            float acc[2][4][4];
            mma_comp2<LDS_A, LDS_K, 4, 4>(adjC, Yt, aoffs, boffs,
                                          a_mrow0, a_ncol0, grp, tig, acc);
#pragma unroll
            for (int mt = 0; mt < 2; mt++) {
#pragma unroll
                for (int half = 0; half < 2; half++) {
                    int i_loc = a_mrow0 + mt * 16 + grp + half * 8;
                    if (i_loc < 50) {
                        __nv_bfloat16* xrow = Xs + (a_s * 64 + i_loc) * LDS_K;
#pragma unroll
                        for (int nt = 0; nt < 4; nt++) {
                            int d = a_ncol0 + nt * 8 + tig * 2;
                            float v0 = fmaxf(acc[mt][nt][half * 2 + 0] + bb[nt][0], 0.f);
                            float v1 = fmaxf(acc[mt][nt][half * 2 + 1] + bb[nt][1], 0.f);
                            __nv_bfloat16 h0 = __float2bfloat16(v0);
                            __nv_bfloat16 h1 = __float2bfloat16(v1);
                            *reinterpret_cast<__nv_bfloat162*>(xrow + d) = __nv_bfloat162{h0, h1};
                            *reinterpret_cast<__nv_bfloat162*>(xrow + 128 + d) =
                                __nv_bfloat162{__float2bfloat16(v0 - __bfloat162float(h0)),
                                               __float2bfloat16(v1 - __bfloat162float(h1))};
                        }
                    }
                }
            }
        }
        __syncthreads();
    }

    // ---- gi = X @ w_ih^T + b_ih, 3 chunks rotated through Ws ----
    for (int j = 0; j < 3; j++) {
        fill_bf16_ca<128, 512>(Ws, wihs + (size_t)j * 128 * 256, tid);
        CP_COMMIT();
        CP_WAIT0();
        __syncthreads();

        float acc[2][4][4];
        mma_comp<4>(Xs, Ws, g_mrow0, g_ncol0, grp, tig, acc);

#pragma unroll
        for (int mt = 0; mt < 2; mt++) {
#pragma unroll
            for (int half = 0; half < 2; half++) {
                int r = g_mrow0 + mt * 16 + grp + half * 8;
                int rl = r & 63;
                if (rl < 50) {
                    size_t grow = m0g + (size_t)(r >> 6) * 50 + rl;
                    float* girow = gi + grow * 384 + j * 128;
#pragma unroll
                    for (int nt = 0; nt < 4; nt++) {
                        int c = g_ncol0 + nt * 8 + tig * 2;
                        float2 v = {acc[mt][nt][half * 2 + 0] + b_ih[j * 128 + c],
                                    acc[mt][nt][half * 2 + 1] + b_ih[j * 128 + c + 1]};
                        *reinterpret_cast<float2*>(girow + c) = v;
                    }
                }
            }
        }
        __syncthreads();
    }
}

// ---------------------------------------------------------------------------
// Fused gh GEMM + GRU gates + fc2. r,z gates in registers; h staged to smem
// (reusing the As region after its final mma read) for the fc2 dot.
// ---------------------------------------------------------------------------
__global__ void __launch_bounds__(256, 2)
gemm_gru(const float* __restrict__ hidden, const __nv_bfloat16* __restrict__ W,
         const float* __restrict__ gi, const float* __restrict__ b_hh,
         const float* __restrict__ w_fc2, const float* __restrict__ b_fc2,
         float* __restrict__ h_out, float* __restrict__ q_out) {
    extern __shared__ __nv_bfloat16 sm[];
    __nv_bfloat16* As = sm;
    __nv_bfloat16* Bs = sm + A_TILE;
    float* Hs = reinterpret_cast<float*>(sm);            // [64][132], overlaps As
    float* Wf = reinterpret_cast<float*>(sm + A_TILE);   // [8][132], overlaps Bs

    int tid = threadIdx.x;
    int wid = tid >> 5, lane = tid & 31;
    int grp = lane >> 2, tig = lane & 3;
    int mrow0 = (wid & 1) * 32;
    int ncol0 = (wid >> 1) * 32;
    size_t m0 = (size_t)blockIdx.x * BM;

    fill_bf16_ca<128, 256>(Bs, W, tid);
    fill_f32split(As, hidden + m0 * 128, tid);
    CP_COMMIT();
    CP_WAIT0();
    __syncthreads();

    float rreg[2][4][4];
    float zreg[2][4][4];

    for (int j = 0; j < 3; j++) {
        float acc[2][4][4];
        mma_comp<4>(As, Bs, mrow0, ncol0, grp, tig, acc);

        if (j == 2) __syncthreads();   // all mma reads of As done before Hs writes

#pragma unroll
        for (int mt = 0; mt < 2; mt++) {
#pragma unroll
            for (int nt = 0; nt < 4; nt++) {
                size_t row0 = m0 + mrow0 + mt * 16 + grp;
                int c = ncol0 + nt * 8 + tig * 2;
                float bb0 = b_hh[j * 128 + c], bb1 = b_hh[j * 128 + c + 1];
                float2 gi0 = *reinterpret_cast<const float2*>(&gi[row0 * 384 + j * 128 + c]);
                float2 gi1 = *reinterpret_cast<const float2*>(&gi[(row0 + 8) * 384 + j * 128 + c]);
                float gh00 = acc[mt][nt][0] + bb0, gh01 = acc[mt][nt][1] + bb1;
                float gh10 = acc[mt][nt][2] + bb0, gh11 = acc[mt][nt][3] + bb1;
                if (j == 0) {
                    rreg[mt][nt][0] = 1.f / (1.f + expf(-(gi0.x + gh00)));
                    rreg[mt][nt][1] = 1.f / (1.f + expf(-(gi0.y + gh01)));
                    rreg[mt][nt][2] = 1.f / (1.f + expf(-(gi1.x + gh10)));
                    rreg[mt][nt][3] = 1.f / (1.f + expf(-(gi1.y + gh11)));
                } else if (j == 1) {
                    zreg[mt][nt][0] = 1.f / (1.f + expf(-(gi0.x + gh00)));
                    zreg[mt][nt][1] = 1.f / (1.f + expf(-(gi0.y + gh01)));
                    zreg[mt][nt][2] = 1.f / (1.f + expf(-(gi1.x + gh10)));
                    zreg[mt][nt][3] = 1.f / (1.f + expf(-(gi1.y + gh11)));
                } else {
                    float n00 = tanhf(gi0.x + rreg[mt][nt][0] * gh00);
                    float n01 = tanhf(gi0.y + rreg[mt][nt][1] * gh01);
                    float n10 = tanhf(gi1.x + rreg[mt][nt][2] * gh10);
                    float n11 = tanhf(gi1.y + rreg[mt][nt][3] * gh11);
                    float2 hv0 = *reinterpret_cast<const float2*>(&hidden[row0 * 128 + c]);
                    float2 hv1 = *reinterpret_cast<const float2*>(&hidden[(row0 + 8) * 128 + c]);
                    float z00 = zreg[mt][nt][0], z01 = zreg[mt][nt][1];
                    float z10 = zreg[mt][nt][2], z11 = zreg[mt][nt][3];
                    float2 o0 = {(1.f - z00) * n00 + z00 * hv0.x,
                                 (1.f - z01) * n01 + z01 * hv0.y};
                    float2 o1 = {(1.f - z10) * n10 + z10 * hv1.x,
                                 (1.f - z11) * n11 + z11 * hv1.y};
                    *reinterpret_cast<float2*>(&h_out[row0 * 128 + c]) = o0;
                    *reinterpret_cast<float2*>(&h_out[(row0 + 8) * 128 + c]) = o1;
                    int lr = mrow0 + mt * 16 + grp;
                    *reinterpret_cast<float2*>(&Hs[lr * 132 + c])       = o0;
                    *reinterpret_cast<float2*>(&Hs[(lr + 8) * 132 + c]) = o1;
                }
            }
        }
        if (j < 2) {
            __syncthreads();
            fill_bf16_ca<128, 256>(Bs, W + (size_t)(j + 1) * 128 * 256, tid);
            CP_COMMIT();
            CP_WAIT0();
            __syncthreads();
        }
    }
    __syncthreads();

    // ---- fc2: q = Hs @ w_fc2^T + b ----
    for (int i = tid; i < 8 * 32; i += 256) {   // Wf fill (float4 units)
        int r = i >> 5, c4 = (i & 31) << 2;
        *reinterpret_cast<float4*>(&Wf[r * 132 + c4]) =
            *reinterpret_cast<const float4*>(&w_fc2[r * 128 + c4]);
    }
    __syncthreads();
#pragma unroll
    for (int o = tid; o < 512; o += 256) {
        int rl = o >> 3, a = o & 7;
        const float* hr = &Hs[rl * 132];
        const float* wr = &Wf[a * 132];
        float acc = 0.f;
#pragma unroll
        for (int k = 0; k < 128; k++) acc += hr[k] * wr[k];
        q_out[(m0 + rl) * 8 + a] = acc + b_fc2[a];
    }
}

// ---------------------------------------------------------------------------
// One-shot setup: weight hi|lo splits + adj split tile. 113 blocks x 256.
// ---------------------------------------------------------------------------
__device__ __forceinline__ void cvt_one(const float* in, __nv_bfloat16* outS, int i) {
    float4 v = reinterpret_cast<const float4*>(in)[i];
    int row = i >> 5, c4 = (i & 31) << 2;
    __nv_bfloat16 h0 = __float2bfloat16(v.x), h1 = __float2bfloat16(v.y);
    __nv_bfloat16 h2 = __float2bfloat16(v.z), h3 = __float2bfloat16(v.w);
    __nv_bfloat16* base = outS + (size_t)row * 256;
    *reinterpret_cast<__nv_bfloat162*>(base + c4)     = __nv_bfloat162{h0, h1};
    *reinterpret_cast<__nv_bfloat162*>(base + c4 + 2) = __nv_bfloat162{h2, h3};
    *reinterpret_cast<__nv_bfloat162*>(base + 128 + c4) =
        __nv_bfloat162{__float2bfloat16(v.x - __bfloat162float(h0)),
                       __float2bfloat16(v.y - __bfloat162float(h1))};
    *reinterpret_cast<__nv_bfloat162*>(base + 128 + c4 + 2) =
        __nv_bfloat162{__float2bfloat16(v.z - __bfloat162float(h2)),
                       __float2bfloat16(v.w - __bfloat162float(h3))};
}

__global__ void setup_all(const float* __restrict__ w_gcn, const float* __restrict__ w_ih,
                          const float* __restrict__ w_hh, const float* __restrict__ adj,
                          __nv_bfloat16* __restrict__ wgs, __nv_bfloat16* __restrict__ wihs,
                          __nv_bfloat16* __restrict__ whhs, __nv_bfloat16* __restrict__ adjcs) {
    int b = blockIdx.x, tid = threadIdx.x;
    if (b < 16) {
        cvt_one(w_gcn, wgs, b * 256 + tid);
    } else if (b < 64) {
        cvt_one(w_ih, wihs, (b - 16) * 256 + tid);
    } else if (b < 112) {
        cvt_one(w_hh, whhs, (b - 64) * 256 + tid);
    } else {
        for (int idx = tid; idx < 64 * 136; idx += 256) {
            int r = idx / 136, k = idx - (idx / 136) * 136;
            int j = (k < 64) ? k : k - 64;
            float v = (k < 128 && r < 50 && j < 50) ? adj[r * 50 + j] : 0.f;
            __nv_bfloat16 h = __float2bfloat16(v);
            adjcs[idx] = (k < 64) ? h : __float2bfloat16(v - __bfloat162float(h));
        }
    }
}

// ---------------------------------------------------------------------------
extern "C" void kernel_launch(void* const* d_in, const int* in_sizes, int n_in,
                              void* d_out, int out_size) {
    const float* inputs   = (const float*)d_in[0];
    const float* hidden   = (const float*)d_in[1];
    const float* norm_adj = (const float*)d_in[2];
    const float* w_gcn    = (const float*)d_in[3];
    const float* b_gcn    = (const float*)d_in[4];
    const float* w_ih     = (const float*)d_in[5];
    const float* b_ih     = (const float*)d_in[6];
    const float* w_hh     = (const float*)d_in[7];
    const float* b_hh     = (const float*)d_in[8];
    const float* w_fc2    = (const float*)d_in[9];
    const float* b_fc2    = (const float*)d_in[10];

    float* out = (float*)d_out;
    float* q_out = out;               // (102400, 8)
    float* h_out = out + QSIZE;       // (102400, 128)

    float* gi;
    __nv_bfloat16 *wgs, *wihs, *whhs, *adjcs;
    cudaGetSymbolAddress((void**)&gi, g_gi);
    cudaGetSymbolAddress((void**)&wgs, g_wgs);
    cudaGetSymbolAddress((void**)&wihs, g_wihs);
    cudaGetSymbolAddress((void**)&whhs, g_whhs);
    cudaGetSymbolAddress((void**)&adjcs, g_adjcs);

    cudaFuncSetAttribute(gcn_fused, cudaFuncAttributeMaxDynamicSharedMemorySize, GCN_SMEM);
    cudaFuncSetAttribute(gemm_gru,  cudaFuncAttributeMaxDynamicSharedMemorySize, GEMM_SMEM);

    setup_all<<<113, 256>>>(w_gcn, w_ih, w_hh, norm_adj, wgs, wihs, whhs, adjcs);

    // Fused 3-pass GCN + gi GEMM
    gcn_fused<<<NBATCH / 2, 512, GCN_SMEM>>>(inputs, wgs, wihs, adjcs, b_gcn, b_ih, gi);

    // gh GEMM + GRU + fc2
    gemm_gru<<<NROWS / BM, 256, GEMM_SMEM>>>(hidden, whhs, gi, b_hh, w_fc2, b_fc2,
                                             h_out, q_out);
}